// round 1
// baseline (speedup 1.0000x reference)
#include <cuda_runtime.h>

// GarNet: B=256, V=1024, F=16, P=16, A=8, NF=32
// out[b,v,n] = mask(v) * ( sum_a ew[v,a] * M[b,a,n] + b_out[n] )
//   ew[v,a]  = mask(v) * 2^(-(data[v]·W_s + b_s)[a])
//   agg[a,p] = (1/V) sum_v ew[v,a] * (data[v]·W_flr + b_flr)[p]
//   M[a,n]   = sum_p agg[a,p] * W_out[a*P+p, n]

#define NB   256
#define NV   1024
#define NFEA 16
#define NP   16
#define NA   8
#define NOUT 32

// Shared-memory layout (floats), with bank-conflict padding:
//  ew:   h0 [0,4096), pad 8, h1 [4104,8200)        (ew4[h][v], float4)
//  feat: [8208, 8208+4*4100)  pg-block stride 4100 (feat4[pg][v], float4, +4 pad/pg)
//  part: [24608,25632)  agg:[25632,25760)  M:[25760,26016)
//  Wf:[26016,26272) Ws:[26272,26400) bf:[26400,26416) bs:[26416,26424) bo:[26424,26456)
#define EW_H1_OFF   4104
#define FEAT_OFF    8208
#define FEAT_STRIDE 4100
#define PART_OFF    24608
#define AGG_OFF     25632
#define M_OFF       25760
#define WF_OFF      26016
#define WS_OFF      26272
#define BF_OFF      26400
#define BS_OFF      26416
#define BO_OFF      26424
#define SMEM_FLOATS 26456
#define SMEM_BYTES  (SMEM_FLOATS * 4)

__global__ void __launch_bounds__(256, 2)
garnet_kernel(const float* __restrict__ data,
              const int*   __restrict__ num_vertex,
              const float* __restrict__ W_flr,
              const float* __restrict__ b_flr,
              const float* __restrict__ W_s,
              const float* __restrict__ b_s,
              const float* __restrict__ W_out,
              const float* __restrict__ b_out,
              float*       __restrict__ out)
{
    extern __shared__ float sm[];
    float4* ew4_h0 = reinterpret_cast<float4*>(sm);
    float4* ew4_h1 = reinterpret_cast<float4*>(sm + EW_H1_OFF);
    float*  feat_f = sm + FEAT_OFF;
    float4* part4  = reinterpret_cast<float4*>(sm + PART_OFF);
    float*  agg_sh = sm + AGG_OFF;
    float*  M_sh   = sm + M_OFF;
    float*  Wf_sh  = sm + WF_OFF;
    float*  Ws_sh  = sm + WS_OFF;
    float*  bf_sh  = sm + BF_OFF;
    float*  bs_sh  = sm + BS_OFF;
    float*  bo_sh  = sm + BO_OFF;

    const int tid = threadIdx.x;
    const int b   = blockIdx.x;

    // ---- stage small weights into shared ----
    Wf_sh[tid] = W_flr[tid];                 // 256 floats
    if (tid < 128) Ws_sh[tid] = W_s[tid];    // 128
    if (tid < 16)  bf_sh[tid] = b_flr[tid];
    if (tid < 8)   bs_sh[tid] = b_s[tid];
    if (tid < 32)  bo_sh[tid] = b_out[tid];
    const int nv = num_vertex[b];
    __syncthreads();

    const float4* data4 = reinterpret_cast<const float4*>(data) + (size_t)b * (NV * NFEA / 4);

    // ================= Phase A: feat + ew (2 vertices / thread / iter) =================
    for (int it = 0; it < 2; ++it) {
        const int v0 = it * 512 + tid;
        const int v1 = v0 + 256;

        float4 q00 = data4[v0 * 4 + 0], q01 = data4[v0 * 4 + 1];
        float4 q02 = data4[v0 * 4 + 2], q03 = data4[v0 * 4 + 3];
        float4 q10 = data4[v1 * 4 + 0], q11 = data4[v1 * 4 + 1];
        float4 q12 = data4[v1 * 4 + 2], q13 = data4[v1 * 4 + 3];

        float dv0[16] = {q00.x,q00.y,q00.z,q00.w, q01.x,q01.y,q01.z,q01.w,
                         q02.x,q02.y,q02.z,q02.w, q03.x,q03.y,q03.z,q03.w};
        float dv1[16] = {q10.x,q10.y,q10.z,q10.w, q11.x,q11.y,q11.z,q11.w,
                         q12.x,q12.y,q12.z,q12.w, q13.x,q13.y,q13.z,q13.w};

        float f0[16], f1[16], s0[8], s1[8];
        #pragma unroll
        for (int p = 0; p < 16; ++p) { float bv = bf_sh[p]; f0[p] = bv; f1[p] = bv; }
        #pragma unroll
        for (int a = 0; a < 8; ++a)  { float bv = bs_sh[a]; s0[a] = bv; s1[a] = bv; }

        #pragma unroll
        for (int f = 0; f < 16; ++f) {
            const float x0 = dv0[f], x1 = dv1[f];
            #pragma unroll
            for (int p = 0; p < 16; ++p) {
                const float w = Wf_sh[f * 16 + p];
                f0[p] += x0 * w; f1[p] += x1 * w;
            }
            #pragma unroll
            for (int a = 0; a < 8; ++a) {
                const float w = Ws_sh[f * 8 + a];
                s0[a] += x0 * w; s1[a] += x1 * w;
            }
        }

        // edge weights: exp(dist * -ln2) == 2^(-dist)
        float e0[8], e1[8];
        const bool m0 = (v0 < nv), m1 = (v1 < nv);
        #pragma unroll
        for (int a = 0; a < 8; ++a) {
            e0[a] = m0 ? exp2f(-s0[a]) : 0.0f;
            e1[a] = m1 ? exp2f(-s1[a]) : 0.0f;
        }

        ew4_h0[v0] = make_float4(e0[0], e0[1], e0[2], e0[3]);
        ew4_h1[v0] = make_float4(e0[4], e0[5], e0[6], e0[7]);
        ew4_h0[v1] = make_float4(e1[0], e1[1], e1[2], e1[3]);
        ew4_h1[v1] = make_float4(e1[4], e1[5], e1[6], e1[7]);

        #pragma unroll
        for (int pg = 0; pg < 4; ++pg) {
            float4* fb = reinterpret_cast<float4*>(feat_f + pg * FEAT_STRIDE);
            fb[v0] = make_float4(f0[4*pg], f0[4*pg+1], f0[4*pg+2], f0[4*pg+3]);
            fb[v1] = make_float4(f1[4*pg], f1[4*pg+1], f1[4*pg+2], f1[4*pg+3]);
        }
    }
    __syncthreads();

    // ================= Phase B: agg[a,p] = (1/V) sum_v ew*feat =================
    {
        const int pairIdx = tid & 31;          // 32 (a, p-group) pairs
        const int a  = pairIdx >> 2;
        const int pg = pairIdx & 3;
        const int split = tid >> 5;            // 8-way split over V
        // ew scalar: float offset h*4104_pad handled: h0 base 0, h1 base EW_H1_OFF
        const int ewbase = ((a >> 2) ? EW_H1_OFF : 0) + (a & 3);
        const float4* fb = reinterpret_cast<const float4*>(feat_f + pg * FEAT_STRIDE);
        float4 acc = make_float4(0.f, 0.f, 0.f, 0.f);
        const int vbase = split * 128;
        #pragma unroll 4
        for (int k = 0; k < 128; ++k) {
            const int v = vbase + k;
            const float  e  = sm[ewbase + v * 4];
            const float4 fv = fb[v];
            acc.x += e * fv.x; acc.y += e * fv.y;
            acc.z += e * fv.z; acc.w += e * fv.w;
        }
        part4[split * 32 + pairIdx] = acc;
    }
    __syncthreads();

    if (tid < 128) {
        const int a = tid >> 4, p = tid & 15;
        const int pi = a * 4 + (p >> 2), c = p & 3;
        float s = 0.f;
        #pragma unroll
        for (int sp = 0; sp < 8; ++sp)
            s += sm[PART_OFF + (sp * 32 + pi) * 4 + c];
        agg_sh[a * 16 + p] = s * (1.0f / 1024.0f);
    }
    __syncthreads();

    // ================= M[a,n] = sum_p agg[a,p] * W_out[a*16+p, n] =================
    {
        const int a = tid >> 5, n = tid & 31;
        float m = 0.f;
        #pragma unroll
        for (int p = 0; p < 16; ++p)
            m += agg_sh[a * 16 + p] * W_out[(a * 16 + p) * 32 + n];
        M_sh[a * 32 + n] = m;
    }
    __syncthreads();

    // ================= Pass 2: out[v,n] = mask*(sum_a ew[v,a]*M[a,n] + b_out[n]) ======
    float4* out4 = reinterpret_cast<float4*>(out) + (size_t)b * (NV * NOUT / 4);
    const float4* M4  = reinterpret_cast<const float4*>(M_sh);
    const float4* bo4 = reinterpret_cast<const float4*>(bo_sh);

    for (int it = 0; it < 2; ++it) {
        const int v0 = it * 512 + tid;
        const int v1 = v0 + 256;

        float4 ea0 = ew4_h0[v0], eb0 = ew4_h1[v0];
        float4 ea1 = ew4_h0[v1], eb1 = ew4_h1[v1];
        float e0[8] = {ea0.x, ea0.y, ea0.z, ea0.w, eb0.x, eb0.y, eb0.z, eb0.w};
        float e1[8] = {ea1.x, ea1.y, ea1.z, ea1.w, eb1.x, eb1.y, eb1.z, eb1.w};

        float4 acc0[8], acc1[8];
        #pragma unroll
        for (int j = 0; j < 8; ++j) {
            float4 bv = bo4[j];
            acc0[j] = bv; acc1[j] = bv;
        }
        #pragma unroll
        for (int a = 0; a < 8; ++a) {
            #pragma unroll
            for (int j = 0; j < 8; ++j) {
                const float4 m = M4[a * 8 + j];
                acc0[j].x += e0[a] * m.x; acc0[j].y += e0[a] * m.y;
                acc0[j].z += e0[a] * m.z; acc0[j].w += e0[a] * m.w;
                acc1[j].x += e1[a] * m.x; acc1[j].y += e1[a] * m.y;
                acc1[j].z += e1[a] * m.z; acc1[j].w += e1[a] * m.w;
            }
        }

        const float4 z = make_float4(0.f, 0.f, 0.f, 0.f);
        if (v0 < nv) {
            #pragma unroll
            for (int j = 0; j < 8; ++j) out4[v0 * 8 + j] = acc0[j];
        } else {
            #pragma unroll
            for (int j = 0; j < 8; ++j) out4[v0 * 8 + j] = z;
        }
        if (v1 < nv) {
            #pragma unroll
            for (int j = 0; j < 8; ++j) out4[v1 * 8 + j] = acc1[j];
        } else {
            #pragma unroll
            for (int j = 0; j < 8; ++j) out4[v1 * 8 + j] = z;
        }
    }
}

extern "C" void kernel_launch(void* const* d_in, const int* in_sizes, int n_in,
                              void* d_out, int out_size)
{
    const float* data       = (const float*)d_in[0];
    const int*   num_vertex = (const int*)  d_in[1];
    const float* W_flr      = (const float*)d_in[2];
    const float* b_flr      = (const float*)d_in[3];
    const float* W_s        = (const float*)d_in[4];
    const float* b_s        = (const float*)d_in[5];
    const float* W_out      = (const float*)d_in[6];
    const float* b_out      = (const float*)d_in[7];
    float*       out        = (float*)d_out;

    (void)in_sizes; (void)n_in; (void)out_size;

    cudaFuncSetAttribute(garnet_kernel,
                         cudaFuncAttributeMaxDynamicSharedMemorySize, SMEM_BYTES);
    garnet_kernel<<<NB, 256, SMEM_BYTES>>>(data, num_vertex, W_flr, b_flr,
                                           W_s, b_s, W_out, b_out, out);
}

// round 2
// speedup vs baseline: 2.7280x; 2.7280x over previous
#include <cuda_runtime.h>

// GarNet: B=256, V=1024, F=16, P=16, A=8, NF=32
// out[b,v,n] = mask(v) * ( sum_a ew[v,a] * M[b,a,n] + b_out[n] )
//   ew[v,a]  = mask(v) * 2^(-(data[v]·W_s + b_s)[a])
//   agg[a,p] = (1/V) sum_v ew[v,a] * (data[v]·W_flr + b_flr)[p]
//   M[a,n]   = sum_p agg[a,p] * W_out[a*P+p, n]
//
// Two-kernel split for occupancy/latency hiding:
//   K1: 2048 blocks x 128 thr: per-vertex feat/ew, ew -> global scratch,
//       block reduction of ew (x) feat over 128 vertices -> partial sums.
//   K2: 2048 blocks x 128 thr: reduce partials -> agg -> M (tiny, redundant),
//       then out[v,:] = mask*(ew[v,:] @ M + b_out).

#define NB   256
#define NV   1024
#define NS   8          // V splits
#define VS   128        // vertices per split
#define NFEA 16
#define NP   16
#define NA   8
#define NOUT 32

#define EWS 132         // smem row stride (floats) for [a][v] / [p][v] layouts

// Global scratch (allocation-free rule: __device__ arrays)
__device__ float g_ew[NB * NV * NA];        // 8 MB
__device__ float g_part[NB * NS * 128];     // 1 MB

// ==================== Kernel 1 ====================
__global__ void __launch_bounds__(128)
garnet_k1(const float* __restrict__ data,
          const int*   __restrict__ num_vertex,
          const float* __restrict__ W_flr,
          const float* __restrict__ b_flr,
          const float* __restrict__ W_s,
          const float* __restrict__ b_s)
{
    __shared__ float Wf_sh[256];
    __shared__ float Ws_sh[128];
    __shared__ float bf_sh[16];
    __shared__ float bs_sh[8];
    __shared__ float red[(NA + NP) * EWS];   // rows 0..7: ew[a][v], rows 8..23: feat[p][v]

    const int t = threadIdx.x;
    const int s = blockIdx.x;      // split
    const int b = blockIdx.y;      // batch
    const int v = s * VS + t;      // this thread's vertex

    Wf_sh[t]       = W_flr[t];
    Wf_sh[t + 128] = W_flr[t + 128];
    Ws_sh[t]       = W_s[t];
    if (t < 16) bf_sh[t] = b_flr[t];
    if (t < 8)  bs_sh[t] = b_s[t];
    const int nv = num_vertex[b];
    __syncthreads();

    // ---- per-vertex: feat[16], dist[8], ew[8] ----
    const float4* data4 = reinterpret_cast<const float4*>(data)
                        + ((size_t)b * NV + v) * (NFEA / 4);
    float4 q0 = data4[0], q1 = data4[1], q2 = data4[2], q3 = data4[3];
    float dv[16] = {q0.x,q0.y,q0.z,q0.w, q1.x,q1.y,q1.z,q1.w,
                    q2.x,q2.y,q2.z,q2.w, q3.x,q3.y,q3.z,q3.w};

    float f[16], sd[8];
    #pragma unroll
    for (int p = 0; p < 16; ++p) f[p] = bf_sh[p];
    #pragma unroll
    for (int a = 0; a < 8; ++a)  sd[a] = bs_sh[a];

    #pragma unroll
    for (int k = 0; k < 16; ++k) {
        const float x = dv[k];
        #pragma unroll
        for (int p = 0; p < 16; ++p) f[p]  += x * Wf_sh[k * 16 + p];
        #pragma unroll
        for (int a = 0; a < 8; ++a)  sd[a] += x * Ws_sh[k * 8 + a];
    }

    const bool m = (v < nv);
    float ew[8];
    #pragma unroll
    for (int a = 0; a < 8; ++a) ew[a] = m ? exp2f(-sd[a]) : 0.0f;

    // ---- ew -> global scratch (coalesced float4 pairs) ----
    float4* ewg4 = reinterpret_cast<float4*>(g_ew + ((size_t)b * NV + v) * NA);
    ewg4[0] = make_float4(ew[0], ew[1], ew[2], ew[3]);
    ewg4[1] = make_float4(ew[4], ew[5], ew[6], ew[7]);

    // ---- stage transposed into smem: red[a][v], red[8+p][v] ----
    #pragma unroll
    for (int a = 0; a < 8; ++a)  red[a * EWS + t] = ew[a];
    #pragma unroll
    for (int p = 0; p < 16; ++p) red[(8 + p) * EWS + t] = f[p];
    __syncthreads();

    // ---- block reduction: thread t owns pair (a = t>>4, p = t&15) ----
    {
        const int a = t >> 4, p = t & 15;
        const float4* er = reinterpret_cast<const float4*>(&red[a * EWS]);
        const float4* fr = reinterpret_cast<const float4*>(&red[(8 + p) * EWS]);
        float4 acc = make_float4(0.f, 0.f, 0.f, 0.f);
        #pragma unroll
        for (int k = 0; k < VS / 4; ++k) {
            const float4 e = er[k];
            const float4 ff = fr[k];
            acc.x += e.x * ff.x; acc.y += e.y * ff.y;
            acc.z += e.z * ff.z; acc.w += e.w * ff.w;
        }
        g_part[((size_t)b * NS + s) * 128 + t] = acc.x + acc.y + acc.z + acc.w;
    }
}

// ==================== Kernel 2 ====================
__global__ void __launch_bounds__(128)
garnet_k2(const int*   __restrict__ num_vertex,
          const float* __restrict__ W_out,
          const float* __restrict__ b_out,
          float*       __restrict__ out)
{
    __shared__ float agg_sh[128];   // agg[a*16+p]
    __shared__ float M_sh[256];     // M[a*32+n]
    __shared__ float bo_sh[32];

    const int t = threadIdx.x;
    const int s = blockIdx.x;
    const int b = blockIdx.y;
    const int v = s * VS + t;

    // ---- reduce partials over splits (L2-hot) ----
    float acc = 0.f;
    #pragma unroll
    for (int sp = 0; sp < NS; ++sp)
        acc += g_part[((size_t)b * NS + sp) * 128 + t];
    agg_sh[t] = acc * (1.0f / (float)NV);
    if (t < 32) bo_sh[t] = b_out[t];
    __syncthreads();

    // ---- M[a,n] = sum_p agg[a,p] * W_out[a*16+p, n]  (2 entries/thread) ----
    #pragma unroll
    for (int e = t; e < 256; e += 128) {
        const int a = e >> 5, n = e & 31;
        float mm = 0.f;
        #pragma unroll
        for (int p = 0; p < 16; ++p)
            mm += agg_sh[a * 16 + p] * W_out[(a * 16 + p) * 32 + n];
        M_sh[e] = mm;
    }
    const int nv = num_vertex[b];
    __syncthreads();

    // ---- per-vertex output ----
    const float4* ewg4 = reinterpret_cast<const float4*>(g_ew + ((size_t)b * NV + v) * NA);
    const float4 e0 = ewg4[0], e1 = ewg4[1];
    const float ew[8] = {e0.x, e0.y, e0.z, e0.w, e1.x, e1.y, e1.z, e1.w};

    const float4* M4  = reinterpret_cast<const float4*>(M_sh);
    const float4* bo4 = reinterpret_cast<const float4*>(bo_sh);

    float4 acc4[8];
    #pragma unroll
    for (int j = 0; j < 8; ++j) acc4[j] = bo4[j];
    #pragma unroll
    for (int a = 0; a < 8; ++a) {
        const float e = ew[a];
        #pragma unroll
        for (int j = 0; j < 8; ++j) {
            const float4 mm = M4[a * 8 + j];
            acc4[j].x += e * mm.x; acc4[j].y += e * mm.y;
            acc4[j].z += e * mm.z; acc4[j].w += e * mm.w;
        }
    }

    float4* out4 = reinterpret_cast<float4*>(out) + ((size_t)b * NV + v) * (NOUT / 4);
    if (v < nv) {
        #pragma unroll
        for (int j = 0; j < 8; ++j) out4[j] = acc4[j];
    } else {
        const float4 z = make_float4(0.f, 0.f, 0.f, 0.f);
        #pragma unroll
        for (int j = 0; j < 8; ++j) out4[j] = z;
    }
}

extern "C" void kernel_launch(void* const* d_in, const int* in_sizes, int n_in,
                              void* d_out, int out_size)
{
    const float* data       = (const float*)d_in[0];
    const int*   num_vertex = (const int*)  d_in[1];
    const float* W_flr      = (const float*)d_in[2];
    const float* b_flr      = (const float*)d_in[3];
    const float* W_s        = (const float*)d_in[4];
    const float* b_s        = (const float*)d_in[5];
    const float* W_out      = (const float*)d_in[6];
    const float* b_out      = (const float*)d_in[7];
    float*       out        = (float*)d_out;

    (void)in_sizes; (void)n_in; (void)out_size;

    dim3 grid(NS, NB);
    garnet_k1<<<grid, 128>>>(data, num_vertex, W_flr, b_flr, W_s, b_s);
    garnet_k2<<<grid, 128>>>(num_vertex, W_out, b_out, out);
}

// round 3
// speedup vs baseline: 3.0642x; 1.1232x over previous
#include <cuda_runtime.h>

// GarNet: B=256, V=1024, F=16, P=16, A=8, NF=32
// out[b,v,n] = mask(v) * ( sum_a ew[v,a] * M[b,a,n] + b_out[n] )
//   ew[v,a]  = mask(v) * 2^(-(data[v]·W_s + b_s)[a])
//   agg[a,p] = (1/V) sum_v ew[v,a] * (data[v]·W_flr + b_flr)[p]
//   M[a,n]   = sum_p agg[a,p] * W_out[a*P+p, n]
//
// Three-kernel pipeline:
//   K1 (8x256 blocks,128t): per-vertex feat/ew, ew->scratch, block-partial agg.
//   Km (256 blocks,128t):   partials -> agg -> M -> g_M (once per batch).
//   K2 (8x256 blocks,128t): out[v,n] = mask*(ew[v,:]@M + b_out), M in registers.

#define NB   256
#define NV   1024
#define NS   8
#define VS   128
#define NFEA 16
#define NP   16
#define NA   8
#define NOUT 32

#define EWS 132

__device__ float g_ew[NB * NV * NA];        // 8 MB
__device__ float g_part[NB * NS * 128];     // 1 MB
__device__ float g_M[NB * NA * NOUT];       // 256 KB

// ==================== Kernel 1 ====================
__global__ void __launch_bounds__(128)
garnet_k1(const float* __restrict__ data,
          const int*   __restrict__ num_vertex,
          const float* __restrict__ W_flr,
          const float* __restrict__ b_flr,
          const float* __restrict__ W_s,
          const float* __restrict__ b_s)
{
    __shared__ float Wf_sh[256];
    __shared__ float Ws_sh[128];
    __shared__ float bf_sh[16];
    __shared__ float bs_sh[8];
    __shared__ float red[(NA + NP) * EWS];

    const int t = threadIdx.x;
    const int s = blockIdx.x;
    const int b = blockIdx.y;
    const int v = s * VS + t;

    Wf_sh[t]       = W_flr[t];
    Wf_sh[t + 128] = W_flr[t + 128];
    Ws_sh[t]       = W_s[t];
    if (t < 16) bf_sh[t] = b_flr[t];
    if (t < 8)  bs_sh[t] = b_s[t];
    const int nv = num_vertex[b];
    __syncthreads();

    const float4* data4 = reinterpret_cast<const float4*>(data)
                        + ((size_t)b * NV + v) * (NFEA / 4);
    float4 q0 = data4[0], q1 = data4[1], q2 = data4[2], q3 = data4[3];
    float dv[16] = {q0.x,q0.y,q0.z,q0.w, q1.x,q1.y,q1.z,q1.w,
                    q2.x,q2.y,q2.z,q2.w, q3.x,q3.y,q3.z,q3.w};

    float f[16], sd[8];
    #pragma unroll
    for (int p = 0; p < 16; ++p) f[p] = bf_sh[p];
    #pragma unroll
    for (int a = 0; a < 8; ++a)  sd[a] = bs_sh[a];

    const float4* Wf4 = reinterpret_cast<const float4*>(Wf_sh);
    const float4* Ws4 = reinterpret_cast<const float4*>(Ws_sh);

    #pragma unroll
    for (int k = 0; k < 16; ++k) {
        const float x = dv[k];
        const float4 w0 = Wf4[k*4+0], w1 = Wf4[k*4+1];
        const float4 w2 = Wf4[k*4+2], w3 = Wf4[k*4+3];
        f[0]  += x*w0.x; f[1]  += x*w0.y; f[2]  += x*w0.z; f[3]  += x*w0.w;
        f[4]  += x*w1.x; f[5]  += x*w1.y; f[6]  += x*w1.z; f[7]  += x*w1.w;
        f[8]  += x*w2.x; f[9]  += x*w2.y; f[10] += x*w2.z; f[11] += x*w2.w;
        f[12] += x*w3.x; f[13] += x*w3.y; f[14] += x*w3.z; f[15] += x*w3.w;
        const float4 u0 = Ws4[k*2+0], u1 = Ws4[k*2+1];
        sd[0] += x*u0.x; sd[1] += x*u0.y; sd[2] += x*u0.z; sd[3] += x*u0.w;
        sd[4] += x*u1.x; sd[5] += x*u1.y; sd[6] += x*u1.z; sd[7] += x*u1.w;
    }

    const bool m = (v < nv);
    float ew[8];
    #pragma unroll
    for (int a = 0; a < 8; ++a) ew[a] = m ? exp2f(-sd[a]) : 0.0f;

    float4* ewg4 = reinterpret_cast<float4*>(g_ew + ((size_t)b * NV + v) * NA);
    ewg4[0] = make_float4(ew[0], ew[1], ew[2], ew[3]);
    ewg4[1] = make_float4(ew[4], ew[5], ew[6], ew[7]);

    #pragma unroll
    for (int a = 0; a < 8; ++a)  red[a * EWS + t] = ew[a];
    #pragma unroll
    for (int p = 0; p < 16; ++p) red[(8 + p) * EWS + t] = f[p];
    __syncthreads();

    {
        const int a = t >> 4, p = t & 15;
        const float4* er = reinterpret_cast<const float4*>(&red[a * EWS]);
        const float4* fr = reinterpret_cast<const float4*>(&red[(8 + p) * EWS]);
        float4 acc = make_float4(0.f, 0.f, 0.f, 0.f);
        #pragma unroll
        for (int k = 0; k < VS / 4; ++k) {
            const float4 e = er[k];
            const float4 ff = fr[k];
            acc.x += e.x * ff.x; acc.y += e.y * ff.y;
            acc.z += e.z * ff.z; acc.w += e.w * ff.w;
        }
        g_part[((size_t)b * NS + s) * 128 + t] = acc.x + acc.y + acc.z + acc.w;
    }
}

// ==================== Kernel Km: agg -> M per batch ====================
__global__ void __launch_bounds__(128)
garnet_km(const float* __restrict__ W_out)
{
    __shared__ float agg_sh[128];
    __shared__ float Wo_sh[NA * NP * NOUT];   // 4096 floats = 16 KB

    const int t = threadIdx.x;
    const int b = blockIdx.x;

    // stage W_out (coalesced float4)
    {
        const float4* src = reinterpret_cast<const float4*>(W_out);
        float4* dst = reinterpret_cast<float4*>(Wo_sh);
        #pragma unroll
        for (int i = 0; i < 8; ++i) dst[t + i * 128] = src[t + i * 128];
    }

    float acc = 0.f;
    #pragma unroll
    for (int sp = 0; sp < NS; ++sp)
        acc += g_part[((size_t)b * NS + sp) * 128 + t];
    agg_sh[t] = acc * (1.0f / (float)NV);
    __syncthreads();

    #pragma unroll
    for (int e = t; e < 256; e += 128) {
        const int a = e >> 5, n = e & 31;
        float mm = 0.f;
        #pragma unroll
        for (int p = 0; p < 16; ++p)
            mm += agg_sh[a * 16 + p] * Wo_sh[(a * 16 + p) * 32 + n];
        g_M[b * 256 + e] = mm;
    }
}

// ==================== Kernel 2: output ====================
__global__ void __launch_bounds__(128)
garnet_k2(const int*   __restrict__ num_vertex,
          const float* __restrict__ b_out,
          float*       __restrict__ out)
{
    __shared__ float4 ew4_sh[VS * 2];   // [v][a] as 2 float4 per vertex
    __shared__ float4 M4_sh[64];        // M[a][n] as float4 groups

    const int t  = threadIdx.x;
    const int s  = blockIdx.x;
    const int b  = blockIdx.y;
    const int ng = t & 7;               // n-group (4 outputs)
    const int vl = t >> 3;              // vertex lane 0..15

    // cooperative loads
    {
        const float4* src = reinterpret_cast<const float4*>(g_ew)
                          + ((size_t)b * NV + s * VS) * 2;
        ew4_sh[t]       = src[t];
        ew4_sh[t + 128] = src[t + 128];
        if (t < 64)
            M4_sh[t] = reinterpret_cast<const float4*>(g_M + b * 256)[t];
    }
    const int nv = num_vertex[b];
    const float4 bo = reinterpret_cast<const float4*>(b_out)[ng];
    __syncthreads();

    // M column (this thread's 4 output channels) in registers
    float4 Mr[8];
    #pragma unroll
    for (int a = 0; a < 8; ++a) Mr[a] = M4_sh[a * 8 + ng];

    float4* out4 = reinterpret_cast<float4*>(out)
                 + ((size_t)b * NV + s * VS) * (NOUT / 4);
    const float4 z = make_float4(0.f, 0.f, 0.f, 0.f);

    #pragma unroll
    for (int k = 0; k < 8; ++k) {
        const int v = vl + k * 16;
        const float4 e0 = ew4_sh[v * 2];
        const float4 e1 = ew4_sh[v * 2 + 1];

        float4 acc = bo;
        acc.x += e0.x*Mr[0].x; acc.y += e0.x*Mr[0].y; acc.z += e0.x*Mr[0].z; acc.w += e0.x*Mr[0].w;
        acc.x += e0.y*Mr[1].x; acc.y += e0.y*Mr[1].y; acc.z += e0.y*Mr[1].z; acc.w += e0.y*Mr[1].w;
        acc.x += e0.z*Mr[2].x; acc.y += e0.z*Mr[2].y; acc.z += e0.z*Mr[2].z; acc.w += e0.z*Mr[2].w;
        acc.x += e0.w*Mr[3].x; acc.y += e0.w*Mr[3].y; acc.z += e0.w*Mr[3].z; acc.w += e0.w*Mr[3].w;
        acc.x += e1.x*Mr[4].x; acc.y += e1.x*Mr[4].y; acc.z += e1.x*Mr[4].z; acc.w += e1.x*Mr[4].w;
        acc.x += e1.y*Mr[5].x; acc.y += e1.y*Mr[5].y; acc.z += e1.y*Mr[5].z; acc.w += e1.y*Mr[5].w;
        acc.x += e1.z*Mr[6].x; acc.y += e1.z*Mr[6].y; acc.z += e1.z*Mr[6].z; acc.w += e1.z*Mr[6].w;
        acc.x += e1.w*Mr[7].x; acc.y += e1.w*Mr[7].y; acc.z += e1.w*Mr[7].z; acc.w += e1.w*Mr[7].w;

        out4[v * 8 + ng] = (s * VS + v < nv) ? acc : z;
    }
}

extern "C" void kernel_launch(void* const* d_in, const int* in_sizes, int n_in,
                              void* d_out, int out_size)
{
    const float* data       = (const float*)d_in[0];
    const int*   num_vertex = (const int*)  d_in[1];
    const float* W_flr      = (const float*)d_in[2];
    const float* b_flr      = (const float*)d_in[3];
    const float* W_s        = (const float*)d_in[4];
    const float* b_s        = (const float*)d_in[5];
    const float* W_out      = (const float*)d_in[6];
    const float* b_out      = (const float*)d_in[7];
    float*       out        = (float*)d_out;

    (void)in_sizes; (void)n_in; (void)out_size;

    dim3 grid(NS, NB);
    garnet_k1<<<grid, 128>>>(data, num_vertex, W_flr, b_flr, W_s, b_s);
    garnet_km<<<NB, 128>>>(W_out);
    garnet_k2<<<grid, 128>>>(num_vertex, b_out, out);
}